// round 14
// baseline (speedup 1.0000x reference)
#include <cuda_runtime.h>
#include <cuda_bf16.h>
#include <math.h>
#include <stdint.h>

#define NSEQ 16130
#define NPAD 16384
#define PADF 254
#define NLM 256
#define DM 512
#define QW 1536
#define HD 64
#define BH 16
#define NTOK 16000
#define NFEAT 16129
#define GR 127
#define NSPL 32
#define KSPL 512

// ---------- static scratch ----------
__device__ float d_h[2ll*NSEQ*DM];
__device__ float d_xln[2ll*NPAD*DM];
__device__ float d_qkv[2ll*NPAD*QW];
__device__ float d_sbuf[(long long)BH*NPAD*NLM];
__device__ float d_ao[2ll*NPAD*DM];
__device__ float d_q[(long long)BH*NPAD*HD];
__device__ float d_k[(long long)BH*NPAD*HD];
__device__ float d_v[(long long)BH*NPAD*HD];
__device__ float d_part[(long long)NSPL*BH*NLM*HD];
__device__ float d_ql[BH*NLM*HD], d_kl[BH*NLM*HD];
__device__ float d_a2[BH*NLM*NLM], d_z[BH*NLM*NLM], d_z2[BH*NLM*NLM];
__device__ float d_az[BH*NLM*NLM], d_tt[BH*NLM*NLM], d_uu[BH*NLM*NLM];
__device__ float d_t3[BH*NLM*HD], d_w[BH*NLM*HD];
__device__ int d_sc[2];

// ---------- BF16 tensor-core GEMM, 128x256 CTA tile, reg-prefetch double-buffered ----------
// C = alpha * A @ B^T (+bias)(+relu); A [M][K] fp32, B [N][K] fp32; bf16 conversion at STS.
// Requires M%128==0, N%256==0, K%16==0, lda/ldb%4==0.
template<int RELU>
__global__ void __launch_bounds__(256, 1) hk2(
    const float* __restrict__ A, const float* __restrict__ B,
    float* __restrict__ C, const float* __restrict__ bias,
    int M, int N, int K, int lda, int ldb, int ldc, float alpha,
    int zm, long long sa1, long long sa2, long long sb1, long long sb2,
    long long sc1, long long sc2)
{
    int z = blockIdx.z, z1 = z % zm, z2 = z / zm;
    A += (long long)z1*sa1 + (long long)z2*sa2;
    B += (long long)z1*sb1 + (long long)z2*sb2;
    C += (long long)z1*sc1 + (long long)z2*sc2;

    __shared__ __nv_bfloat16 As[2][128][24];
    __shared__ __nv_bfloat16 Bs[2][256][24];

    int tid = threadIdx.x, lane = tid & 31, warp = tid >> 5;
    int wm = warp & 1, wn = warp >> 1;          // 2x4 warp grid: warp tile 64x64
    int m0 = blockIdx.y*128, n0 = blockIdx.x*256;

    float acc[4][8][4];
    #pragma unroll
    for (int a = 0; a < 4; a++)
        #pragma unroll
        for (int b = 0; b < 8; b++)
            #pragma unroll
            for (int cc = 0; cc < 4; cc++) acc[a][b][cc] = 0.f;

    float4 ra[2], rb[4];
    auto ldgT = [&](int k0) {
        #pragma unroll
        for (int j = 0; j < 2; j++) {
            int id = tid + j*256;
            int mm = id >> 2, kc = (id & 3)*4;
            ra[j] = *(const float4*)(A + (long long)(m0+mm)*lda + k0 + kc);
        }
        #pragma unroll
        for (int j = 0; j < 4; j++) {
            int id = tid + j*256;
            int nn = id >> 2, kc = (id & 3)*4;
            rb[j] = *(const float4*)(B + (long long)(n0+nn)*ldb + k0 + kc);
        }
    };
    auto stsT = [&](int st) {
        #pragma unroll
        for (int j = 0; j < 2; j++) {
            int id = tid + j*256;
            int mm = id >> 2, kc = (id & 3)*4;
            __nv_bfloat162* da = (__nv_bfloat162*)&As[st][mm][kc];
            da[0] = __float22bfloat162_rn(make_float2(ra[j].x, ra[j].y));
            da[1] = __float22bfloat162_rn(make_float2(ra[j].z, ra[j].w));
        }
        #pragma unroll
        for (int j = 0; j < 4; j++) {
            int id = tid + j*256;
            int nn = id >> 2, kc = (id & 3)*4;
            __nv_bfloat162* db = (__nv_bfloat162*)&Bs[st][nn][kc];
            db[0] = __float22bfloat162_rn(make_float2(rb[j].x, rb[j].y));
            db[1] = __float22bfloat162_rn(make_float2(rb[j].z, rb[j].w));
        }
    };

    int nk = K >> 4;
    ldgT(0);
    stsT(0);
    __syncthreads();

    int r = lane >> 2, c = lane & 3;
    for (int kt = 0; kt < nk; kt++) {
        int cur = kt & 1;
        if (kt + 1 < nk) ldgT((kt+1)*16);
        uint32_t af[4][4];
        #pragma unroll
        for (int mt = 0; mt < 4; mt++) {
            int mb = wm*64 + mt*16;
            af[mt][0] = *(const uint32_t*)&As[cur][mb+r  ][c*2];
            af[mt][1] = *(const uint32_t*)&As[cur][mb+r+8][c*2];
            af[mt][2] = *(const uint32_t*)&As[cur][mb+r  ][c*2+8];
            af[mt][3] = *(const uint32_t*)&As[cur][mb+r+8][c*2+8];
        }
        #pragma unroll
        for (int nt = 0; nt < 8; nt++) {
            int nb = wn*64 + nt*8;
            uint32_t b0 = *(const uint32_t*)&Bs[cur][nb+r][c*2];
            uint32_t b1 = *(const uint32_t*)&Bs[cur][nb+r][c*2+8];
            #pragma unroll
            for (int mt = 0; mt < 4; mt++) {
                asm volatile(
                    "mma.sync.aligned.m16n8k16.row.col.f32.bf16.bf16.f32 "
                    "{%0,%1,%2,%3}, {%4,%5,%6,%7}, {%8,%9}, {%0,%1,%2,%3};"
                    : "+f"(acc[mt][nt][0]), "+f"(acc[mt][nt][1]),
                      "+f"(acc[mt][nt][2]), "+f"(acc[mt][nt][3])
                    : "r"(af[mt][0]), "r"(af[mt][1]), "r"(af[mt][2]), "r"(af[mt][3]),
                      "r"(b0), "r"(b1));
            }
        }
        if (kt + 1 < nk) stsT(cur ^ 1);
        __syncthreads();
    }
    int c2 = (lane & 3)*2;
    #pragma unroll
    for (int mt = 0; mt < 4; mt++) {
        #pragma unroll
        for (int nt = 0; nt < 8; nt++) {
            int row = m0 + wm*64 + mt*16 + r;
            int col = n0 + wn*64 + nt*8 + c2;
            float bv0 = bias ? bias[col] : 0.f;
            float bv1 = bias ? bias[col+1] : 0.f;
            float v0 = alpha*acc[mt][nt][0] + bv0;
            float v1 = alpha*acc[mt][nt][1] + bv1;
            float v2 = alpha*acc[mt][nt][2] + bv0;
            float v3 = alpha*acc[mt][nt][3] + bv1;
            if (RELU) { v0=fmaxf(v0,0.f); v1=fmaxf(v1,0.f); v2=fmaxf(v2,0.f); v3=fmaxf(v3,0.f); }
            C[(long long)row*ldc + col]       = v0;
            C[(long long)row*ldc + col+1]     = v1;
            C[(long long)(row+8)*ldc + col]   = v2;
            C[(long long)(row+8)*ldc + col+1] = v3;
        }
    }
}

// ---------- TF32 tensor-core GEMM (pinv chain / NN shapes / attn2) ----------
template<int TB, int RELU, int BN, int DB>
__global__ void __launch_bounds__(256) tk(
    const float* __restrict__ A, const float* __restrict__ B,
    float* __restrict__ C, const float* __restrict__ bias,
    int M, int N, int K, int lda, int ldb, int ldc, float alpha, float cd,
    int zm, long long sa1, long long sa2, long long sb1, long long sb2,
    long long sc1, long long sc2)
{
    int z = blockIdx.z, z1 = z % zm, z2 = z / zm;
    A += (long long)z1*sa1 + (long long)z2*sa2;
    B += (long long)z1*sb1 + (long long)z2*sb2;
    C += (long long)z1*sc1 + (long long)z2*sc2;

    __shared__ float As[2][128][20];
    constexpr int BS_R = TB ? BN : 16;
    constexpr int BS_C = TB ? 20 : (BN + 8);
    __shared__ float Bs[2][BS_R][BS_C];
    constexpr int NB4 = BN/64;

    int tid = threadIdx.x, lane = tid & 31, warp = tid >> 5;
    int wm = warp & 3, wn = warp >> 2;
    constexpr int WN = BN/2, NT = WN/8;
    int m0 = blockIdx.y*128, n0 = blockIdx.x*BN;

    float acc[2][NT][4];
    #pragma unroll
    for (int a = 0; a < 2; a++)
        #pragma unroll
        for (int b = 0; b < NT; b++)
            #pragma unroll
            for (int cc = 0; cc < 4; cc++) acc[a][b][cc] = 0.f;

    float4 ra[2], rb[NB4];
    auto ldgT = [&](int k0) {
        #pragma unroll
        for (int j = 0; j < 2; j++) {
            int id = tid + j*256;
            int mm = id >> 2, kc = (id & 3)*4;
            ra[j] = *(const float4*)(A + (long long)(m0+mm)*lda + k0 + kc);
        }
        if (TB) {
            #pragma unroll
            for (int j = 0; j < NB4; j++) {
                int id = tid + j*256;
                int nn = id >> 2, kc = (id & 3)*4;
                rb[j] = *(const float4*)(B + (long long)(n0+nn)*ldb + k0 + kc);
            }
        } else {
            #pragma unroll
            for (int j = 0; j < NB4; j++) {
                int id = tid + j*256;
                int kk = id / (BN/4), nc = (id % (BN/4))*4;
                rb[j] = *(const float4*)(B + (long long)(k0+kk)*ldb + n0 + nc);
            }
        }
    };
    auto stsT = [&](int st) {
        #pragma unroll
        for (int j = 0; j < 2; j++) {
            int id = tid + j*256;
            int mm = id >> 2, kc = (id & 3)*4;
            *(float4*)&As[st][mm][kc] = ra[j];
        }
        if (TB) {
            #pragma unroll
            for (int j = 0; j < NB4; j++) {
                int id = tid + j*256;
                int nn = id >> 2, kc = (id & 3)*4;
                *(float4*)&Bs[st][nn][kc] = rb[j];
            }
        } else {
            #pragma unroll
            for (int j = 0; j < NB4; j++) {
                int id = tid + j*256;
                int kk = id / (BN/4), nc = (id % (BN/4))*4;
                *(float4*)&Bs[st][kk][nc] = rb[j];
            }
        }
    };

    int nk = K >> 4;
    ldgT(0);
    stsT(0);
    __syncthreads();

    for (int kt = 0; kt < nk; kt++) {
        int cur = kt & 1;
        if (kt + 1 < nk) ldgT((kt+1)*16);
        int k0 = kt*16;
        int r = lane >> 2, c = lane & 3;
        #pragma unroll
        for (int ks = 0; ks < 2; ks++) {
            int kb = ks*8;
            uint32_t af[2][4];
            #pragma unroll
            for (int mt = 0; mt < 2; mt++) {
                int mb = wm*32 + mt*16;
                af[mt][0] = __float_as_uint(As[cur][mb+r  ][kb+c  ]);
                af[mt][1] = __float_as_uint(As[cur][mb+r+8][kb+c  ]);
                af[mt][2] = __float_as_uint(As[cur][mb+r  ][kb+c+4]);
                af[mt][3] = __float_as_uint(As[cur][mb+r+8][kb+c+4]);
            }
            #pragma unroll
            for (int nt = 0; nt < NT; nt++) {
                int nb = wn*WN + nt*8;
                uint32_t b0, b1;
                if (TB) {
                    b0 = __float_as_uint(Bs[cur][nb+r][kb+c  ]);
                    b1 = __float_as_uint(Bs[cur][nb+r][kb+c+4]);
                } else {
                    float f0 = Bs[cur][kb+c  ][nb+r];
                    float f1 = Bs[cur][kb+c+4][nb+r];
                    if (DB) {
                        int ng = n0 + nb + r;
                        f0 = ((k0+kb+c  ) == ng ? cd : 0.f) - f0;
                        f1 = ((k0+kb+c+4) == ng ? cd : 0.f) - f1;
                    }
                    b0 = __float_as_uint(f0);
                    b1 = __float_as_uint(f1);
                }
                #pragma unroll
                for (int mt = 0; mt < 2; mt++) {
                    asm volatile(
                        "mma.sync.aligned.m16n8k8.row.col.f32.tf32.tf32.f32 "
                        "{%0,%1,%2,%3}, {%4,%5,%6,%7}, {%8,%9}, {%0,%1,%2,%3};"
                        : "+f"(acc[mt][nt][0]), "+f"(acc[mt][nt][1]),
                          "+f"(acc[mt][nt][2]), "+f"(acc[mt][nt][3])
                        : "r"(af[mt][0]), "r"(af[mt][1]), "r"(af[mt][2]), "r"(af[mt][3]),
                          "r"(b0), "r"(b1));
                }
            }
        }
        if (kt + 1 < nk) stsT(cur ^ 1);
        __syncthreads();
    }
    int r = lane >> 2, c2 = (lane & 3)*2;
    #pragma unroll
    for (int mt = 0; mt < 2; mt++) {
        #pragma unroll
        for (int nt = 0; nt < NT; nt++) {
            int row = m0 + wm*32 + mt*16 + r;
            int col = n0 + wn*WN + nt*8 + c2;
            float bv0 = bias ? bias[col] : 0.f;
            float bv1 = bias ? bias[col+1] : 0.f;
            float v0 = alpha*acc[mt][nt][0] + bv0;
            float v1 = alpha*acc[mt][nt][1] + bv1;
            float v2 = alpha*acc[mt][nt][2] + bv0;
            float v3 = alpha*acc[mt][nt][3] + bv1;
            if (RELU) { v0=fmaxf(v0,0.f); v1=fmaxf(v1,0.f); v2=fmaxf(v2,0.f); v3=fmaxf(v3,0.f); }
            C[(long long)row*ldc + col]       = v0;
            C[(long long)row*ldc + col+1]     = v1;
            C[(long long)(row+8)*ldc + col]   = v2;
            C[(long long)(row+8)*ldc + col+1] = v3;
        }
    }
}

// ---------- small kernels ----------
__global__ void k_buildh(const float* __restrict__ fc1o, const float* __restrict__ cls) {
    long long idx = blockIdx.x*256ll + threadIdx.x;
    if (idx >= 2ll*NSEQ*DM) return;
    int c = (int)(idx % DM); long long r = idx / DM; int b = (int)(r / NSEQ); int i = (int)(r % NSEQ);
    float v;
    if (i == 0) v = cls[c];
    else { int t = i-1; if (t >= NTOK) t -= NTOK; v = fc1o[((long long)b*NTOK + t)*DM + c]; }
    d_h[idx] = v;
}

__global__ void k_lnpad(const float* __restrict__ w, const float* __restrict__ bia) {
    int r = blockIdx.x; int b = r / NPAD, rr = r % NPAD;
    float* o = d_xln + (long long)r*DM;
    int t = threadIdx.x;
    if (rr < PADF) { o[t] = 0.f; o[t+256] = 0.f; return; }
    const float* in = d_h + ((long long)b*NSEQ + rr - PADF)*DM;
    __shared__ float red[256];
    float v0 = in[t], v1 = in[t+256];
    red[t] = v0+v1; __syncthreads();
    for (int s = 128; s > 0; s >>= 1) { if (t < s) red[t] += red[t+s]; __syncthreads(); }
    float mu = red[0]*(1.f/DM); __syncthreads();
    float e0 = v0-mu, e1 = v1-mu;
    red[t] = e0*e0+e1*e1; __syncthreads();
    for (int s = 128; s > 0; s >>= 1) { if (t < s) red[t] += red[t+s]; __syncthreads(); }
    float rstd = rsqrtf(red[0]*(1.f/DM) + 1e-5f);
    o[t]     = e0*rstd*w[t]     + bia[t];
    o[t+256] = e1*rstd*w[t+256] + bia[t+256];
}

__global__ void k_splitqkv4() {
    long long idx = blockIdx.x*256ll + threadIdx.x;
    if (idx >= 2ll*NPAD*DM/4) return;
    int c4 = (int)(idx % 128);
    long long bn = idx / 128;
    int hh = c4 >> 4, d4 = c4 & 15;
    int b = (int)(bn / NPAD), n = (int)(bn % NPAD);
    const float4* src = (const float4*)(d_qkv + bn*QW) + c4;
    long long dst = (((long long)(b*8+hh)*NPAD) + n)*(HD/4) + d4;
    ((float4*)d_q)[dst] = src[0];
    ((float4*)d_k)[dst] = src[DM/4];
    ((float4*)d_v)[dst] = src[2*DM/4];
}

__global__ void k_lm() {
    int z = blockIdx.y, j = blockIdx.x, dd = threadIdx.x;
    const float* q = d_q + ((long long)z*NPAD + j*64)*HD + dd;
    const float* k = d_k + ((long long)z*NPAD + j*64)*HD + dd;
    float sq = 0.f, sk = 0.f;
    #pragma unroll 8
    for (int i = 0; i < 64; i++) { sq += q[i*HD]; sk += k[i*HD]; }
    d_ql[(z*NLM+j)*HD+dd] = sq*(1.f/64.f);
    d_kl[(z*NLM+j)*HD+dd] = sk*(1.f/64.f);
}

__global__ void __launch_bounds__(512) k_sm16k(float* __restrict__ p) {
    float4* p4 = (float4*)(p + (long long)blockIdx.x * NPAD);
    int t = threadIdx.x;
    __shared__ float red[512];
    float4 va[8];
    float m = -1e30f;
    #pragma unroll
    for (int j = 0; j < 8; j++) {
        va[j] = p4[t + j*512];
        m = fmaxf(m, fmaxf(fmaxf(va[j].x, va[j].y), fmaxf(va[j].z, va[j].w)));
    }
    red[t] = m; __syncthreads();
    for (int s = 256; s > 0; s >>= 1) { if (t < s) red[t] = fmaxf(red[t], red[t+s]); __syncthreads(); }
    m = red[0]; __syncthreads();
    float sum = 0.f;
    #pragma unroll
    for (int j = 0; j < 8; j++) {
        va[j].x = __expf(va[j].x - m); va[j].y = __expf(va[j].y - m);
        va[j].z = __expf(va[j].z - m); va[j].w = __expf(va[j].w - m);
        sum += (va[j].x + va[j].y) + (va[j].z + va[j].w);
    }
    red[t] = sum; __syncthreads();
    for (int s = 256; s > 0; s >>= 1) { if (t < s) red[t] += red[t+s]; __syncthreads(); }
    float inv = 1.f/red[0];
    #pragma unroll
    for (int j = 0; j < 8; j++) {
        va[j].x *= inv; va[j].y *= inv; va[j].z *= inv; va[j].w *= inv;
        p4[t + j*512] = va[j];
    }
}

__global__ void k_sm256w(float* __restrict__ p, long long nrows) {
    long long row = blockIdx.x*8ll + (threadIdx.x >> 5);
    if (row >= nrows) return;
    int lane = threadIdx.x & 31;
    float4* p4 = (float4*)(p + row*NLM);
    float4 u0 = p4[lane], u1 = p4[lane+32];
    float m = fmaxf(fmaxf(fmaxf(u0.x,u0.y),fmaxf(u0.z,u0.w)),
                    fmaxf(fmaxf(u1.x,u1.y),fmaxf(u1.z,u1.w)));
    #pragma unroll
    for (int s = 16; s > 0; s >>= 1) m = fmaxf(m, __shfl_xor_sync(0xffffffffu, m, s));
    u0.x=__expf(u0.x-m); u0.y=__expf(u0.y-m); u0.z=__expf(u0.z-m); u0.w=__expf(u0.w-m);
    u1.x=__expf(u1.x-m); u1.y=__expf(u1.y-m); u1.z=__expf(u1.z-m); u1.w=__expf(u1.w-m);
    float sum = (u0.x+u0.y)+(u0.z+u0.w)+(u1.x+u1.y)+(u1.z+u1.w);
    #pragma unroll
    for (int s = 16; s > 0; s >>= 1) sum += __shfl_xor_sync(0xffffffffu, sum, s);
    float inv = 1.f/sum;
    u0.x*=inv; u0.y*=inv; u0.z*=inv; u0.w*=inv;
    u1.x*=inv; u1.y*=inv; u1.z*=inv; u1.w*=inv;
    p4[lane] = u0; p4[lane+32] = u1;
}

__global__ void k_init() { d_sc[0] = 0; d_sc[1] = 0; }

__global__ void k_rmax() {
    int mb = blockIdx.x >> 8, i = blockIdx.x & 255, t = threadIdx.x;
    __shared__ float red[256];
    red[t] = fabsf(d_a2[((long long)mb*256+i)*256 + t]); __syncthreads();
    for (int s = 128; s > 0; s >>= 1) { if (t < s) red[t] += red[t+s]; __syncthreads(); }
    if (t == 0) atomicMax(&d_sc[0], __float_as_int(red[0]));
}

__global__ void k_cmax() {
    int mb = blockIdx.x, j = threadIdx.x;
    float s = 0.f;
    for (int i = 0; i < 256; i++) s += fabsf(d_a2[((long long)mb*256+i)*256 + j]);
    atomicMax(&d_sc[1], __float_as_int(s));
}

__global__ void k_tz() {
    long long idx = blockIdx.x*256ll + threadIdx.x;
    if (idx >= (long long)BH*65536) return;
    int mb = (int)(idx >> 16); int r = (int)((idx >> 8) & 255); int c = (int)(idx & 255);
    float sc = __int_as_float(d_sc[0]) * __int_as_float(d_sc[1]);
    d_z[idx] = d_a2[(long long)mb*65536 + (long long)c*256 + r] / sc;
}

__global__ void k_red() {
    int idx = blockIdx.x*256 + threadIdx.x;
    if (idx >= BH*NLM*HD) return;
    float s = 0.f;
    #pragma unroll
    for (int p = 0; p < NSPL; p++) s += d_part[(long long)p*BH*NLM*HD + idx];
    d_t3[idx] = s;
}

__global__ void k_dw(const float* __restrict__ w) {
    int z = blockIdx.y; int b = z >> 3, hh = z & 7;
    int i = blockIdx.x*4 + threadIdx.y;
    int dd = threadIdx.x;
    const float* v = d_v + (long long)z*NPAD*HD + dd;
    float s = 0.f;
    #pragma unroll
    for (int tp = 0; tp < 33; tp++) {
        int ii = i + tp - 16;
        if (ii >= 0 && ii < NPAD) s += w[hh*33+tp] * v[(long long)ii*HD];
    }
    d_ao[((long long)b*NPAD + i)*DM + hh*HD + dd] += s;
}

__global__ void k_radd() {
    long long idx = blockIdx.x*256ll + threadIdx.x;
    if (idx >= 2ll*NSEQ*DM) return;
    int c = (int)(idx % DM); long long r = idx / DM; int b = (int)(r / NSEQ); int i = (int)(r % NSEQ);
    d_h[idx] += d_xln[((long long)b*NPAD + PADF + i)*DM + c];
}

__global__ void k_ppeg(const float* __restrict__ w7, const float* __restrict__ b7,
                       const float* __restrict__ w5, const float* __restrict__ b5,
                       const float* __restrict__ w3, const float* __restrict__ b3) {
    int p = blockIdx.x, b = blockIdx.y, c = threadIdx.x;
    int r = p / GR, ww = p % GR;
    const float* base = d_h + ((long long)b*NSEQ + 1)*DM + c;
    float acc = base[(long long)p*DM] + b7[c] + b5[c] + b3[c];
    for (int i = 0; i < 7; i++) {
        int rr = r + i - 3; if (rr < 0 || rr >= GR) continue;
        for (int j = 0; j < 7; j++) {
            int cc = ww + j - 3; if (cc < 0 || cc >= GR) continue;
            float x = base[(long long)(rr*GR+cc)*DM];
            acc += w7[c*49 + i*7 + j] * x;
            if (i >= 1 && i < 6 && j >= 1 && j < 6) acc += w5[c*25 + (i-1)*5 + (j-1)] * x;
            if (i >= 2 && i < 5 && j >= 2 && j < 5) acc += w3[c*9 + (i-2)*3 + (j-2)] * x;
        }
    }
    d_xln[((long long)b*NFEAT + p)*DM + c] = acc;
}

__global__ void k_ppcp() {
    long long idx = blockIdx.x*256ll + threadIdx.x;
    if (idx >= 2ll*NFEAT*DM) return;
    int c = (int)(idx % DM); long long r = idx / DM; int b = (int)(r / NFEAT); int p = (int)(r % NFEAT);
    d_h[((long long)b*NSEQ + 1 + p)*DM + c] = d_xln[idx];
}

__global__ void k_head(const float* __restrict__ nw, const float* __restrict__ nb,
                       const float* __restrict__ f2w, const float* __restrict__ f2b,
                       float* __restrict__ out) {
    int b = blockIdx.x, t = threadIdx.x;
    const float* x = d_h + (long long)b*NSEQ*DM;
    __shared__ float red[256];
    float v0 = x[t], v1 = x[t+256];
    red[t] = v0+v1; __syncthreads();
    for (int s = 128; s > 0; s >>= 1) { if (t < s) red[t] += red[t+s]; __syncthreads(); }
    float mu = red[0]*(1.f/DM); __syncthreads();
    float e0 = v0-mu, e1 = v1-mu;
    red[t] = e0*e0+e1*e1; __syncthreads();
    for (int s = 128; s > 0; s >>= 1) { if (t < s) red[t] += red[t+s]; __syncthreads(); }
    float rstd = rsqrtf(red[0]*(1.f/DM) + 1e-5f);
    __syncthreads();
    float n0 = e0*rstd*nw[t] + nb[t], n1 = e1*rstd*nw[t+256] + nb[t+256];
    for (int j = 0; j < 2; j++) {
        red[t] = n0*f2w[j*DM+t] + n1*f2w[j*DM+t+256]; __syncthreads();
        for (int s = 128; s > 0; s >>= 1) { if (t < s) red[t] += red[t+s]; __syncthreads(); }
        if (t == 0) out[b*2+j] = red[0] + f2b[j];
        __syncthreads();
    }
}

// ---------- host wrappers ----------
static inline void HK(int RELU, const float* A, const float* B, float* C, const float* bias,
                      int M, int N, int K, int lda, int ldb, int ldc, float al,
                      int Z, int zm,
                      long long a1, long long a2, long long b1, long long b2,
                      long long c1, long long c2) {
    dim3 g(N/256, M/128, Z);
    if (RELU) hk2<1><<<g,256>>>(A,B,C,bias,M,N,K,lda,ldb,ldc,al,zm,a1,a2,b1,b2,c1,c2);
    else      hk2<0><<<g,256>>>(A,B,C,bias,M,N,K,lda,ldb,ldc,al,zm,a1,a2,b1,b2,c1,c2);
}
static inline void TK(int TB, int RELU, int DB,
                      const float* A, const float* B, float* C, const float* bias,
                      int M, int N, int K, int lda, int ldb, int ldc, float al, float cd,
                      int Z, int zm,
                      long long a1, long long a2, long long b1, long long b2,
                      long long c1, long long c2) {
    if (N % 128 == 0) {
        dim3 g(N/128, M/128, Z);
        if (TB && RELU) tk<1,1,128,0><<<g,256>>>(A,B,C,bias,M,N,K,lda,ldb,ldc,al,cd,zm,a1,a2,b1,b2,c1,c2);
        else if (TB)    tk<1,0,128,0><<<g,256>>>(A,B,C,bias,M,N,K,lda,ldb,ldc,al,cd,zm,a1,a2,b1,b2,c1,c2);
        else if (DB)    tk<0,0,128,1><<<g,256>>>(A,B,C,bias,M,N,K,lda,ldb,ldc,al,cd,zm,a1,a2,b1,b2,c1,c2);
        else            tk<0,0,128,0><<<g,256>>>(A,B,C,bias,M,N,K,lda,ldb,ldc,al,cd,zm,a1,a2,b1,b2,c1,c2);
    } else {
        dim3 g(N/64, M/128, Z);
        tk<0,0,64,0><<<g,256>>>(A,B,C,bias,M,N,K,lda,ldb,ldc,al,cd,zm,a1,a2,b1,b2,c1,c2);
    }
}

extern "C" void kernel_launch(void* const* d_in, const int* in_sizes, int n_in,
                              void* d_out, int out_size) {
    const float* x    = (const float*)d_in[0];
    const float* fc1w = (const float*)d_in[1];
    const float* fc1b = (const float*)d_in[2];
    const float* cls  = (const float*)d_in[3];
    const float* lnw  = (const float*)d_in[4];
    const float* lnb  = (const float*)d_in[5];
    const float* qkvw = (const float*)d_in[6];
    const float* qkvb = (const float*)d_in[7];
    const float* aow  = (const float*)d_in[8];
    const float* aob  = (const float*)d_in[9];
    const float* rcw  = (const float*)d_in[10];
    const float* w7 = (const float*)d_in[11]; const float* b7 = (const float*)d_in[12];
    const float* w5 = (const float*)d_in[13]; const float* b5 = (const float*)d_in[14];
    const float* w3 = (const float*)d_in[15]; const float* b3 = (const float*)d_in[16];
    const float* nw = (const float*)d_in[17]; const float* nb = (const float*)d_in[18];
    const float* f2w = (const float*)d_in[19]; const float* f2b = (const float*)d_in[20];
    float* out = (float*)d_out;

    float *xln, *qkv, *sbuf, *ao, *q, *k, *v, *part;
    float *ql, *kl, *a2, *z, *z2, *az, *tt, *uu, *t3, *w;
    cudaGetSymbolAddress((void**)&xln, d_xln);
    cudaGetSymbolAddress((void**)&qkv, d_qkv);
    cudaGetSymbolAddress((void**)&sbuf, d_sbuf);
    cudaGetSymbolAddress((void**)&ao, d_ao);
    cudaGetSymbolAddress((void**)&q, d_q);
    cudaGetSymbolAddress((void**)&k, d_k);
    cudaGetSymbolAddress((void**)&v, d_v);
    cudaGetSymbolAddress((void**)&part, d_part);
    cudaGetSymbolAddress((void**)&ql, d_ql);
    cudaGetSymbolAddress((void**)&kl, d_kl);
    cudaGetSymbolAddress((void**)&a2, d_a2);
    cudaGetSymbolAddress((void**)&z, d_z);
    cudaGetSymbolAddress((void**)&z2, d_z2);
    cudaGetSymbolAddress((void**)&az, d_az);
    cudaGetSymbolAddress((void**)&tt, d_tt);
    cudaGetSymbolAddress((void**)&uu, d_uu);
    cudaGetSymbolAddress((void**)&t3, d_t3);
    cudaGetSymbolAddress((void**)&w, d_w);

    const long long SQ  = (long long)NPAD*QW;
    const long long SD  = (long long)NPAD*DM;
    const long long SH  = (long long)NPAD*HD;
    const long long SS3 = (long long)NLM*NPAD;
    const long long SS1 = (long long)NPAD*NLM;

    // fc1 + relu (bf16) -> sbuf (32000,512); then assemble token stream h
    HK(1, x, fc1w, sbuf, fc1b, 2*NTOK, DM, 1024, 1024, 1024, DM, 1.f, 1,1, 0,0,0,0,0,0);
    k_buildh<<<(int)((2ll*NSEQ*DM+255)/256),256>>>(sbuf, cls);

    for (int l = 0; l < 2; l++) {
        k_lnpad<<<2*NPAD,256>>>(lnw + l*DM, lnb + l*DM);
        HK(0, xln, qkvw + (long long)l*QW*DM, qkv, qkvb + l*QW,
           NPAD, QW, DM, DM, DM, QW, 1.f, 2,2, SD,0, 0,0, SQ,0);
        k_splitqkv4<<<(int)((2ll*NPAD*DM/4+255)/256),256>>>();
        k_lm<<<dim3(256,16),64>>>();
        // attn2 = softmax(0.125 * ql @ kl^T)  (TF32)
        TK(1,0,0, ql, kl, a2, 0, NLM, NLM, HD, HD, HD, NLM, 0.125f, 0.f, BH,BH,
           NLM*HD,0, NLM*HD,0, NLM*NLM,0);
        k_sm256w<<<(int)((BH*NLM+7)/8),256>>>(a2, (long long)BH*NLM);
        // pinv(attn2) (TF32, elementwise fused into B fragment loads)
        k_init<<<1,1>>>();
        k_rmax<<<BH*NLM,256>>>();
        k_cmax<<<BH,256>>>();
        k_tz<<<(BH*65536+255)/256,256>>>();
        float* zc = z; float* zn = z2;
        for (int it = 0; it < 6; it++) {
            TK(0,0,0, a2, zc, az, 0, NLM,NLM,NLM, NLM,NLM,NLM, 1.f, 0.f, BH,BH, 65536,0,65536,0,65536,0);
            TK(0,0,1, az, az, tt, 0, NLM,NLM,NLM, NLM,NLM,NLM, 1.f, 7.f, BH,BH, 65536,0,65536,0,65536,0);
            TK(0,0,1, az, tt, uu, 0, NLM,NLM,NLM, NLM,NLM,NLM, 1.f, 15.f, BH,BH, 65536,0,65536,0,65536,0);
            TK(0,0,1, zc, uu, zn, 0, NLM,NLM,NLM, NLM,NLM,NLM, 0.25f, 13.f, BH,BH, 65536,0,65536,0,65536,0);
            float* sw = zc; zc = zn; zn = sw;
        }
        // S3 = softmax(0.125 * ql @ k^T)   [z][256][16384]  (bf16 GEMM)
        HK(0, ql, k, sbuf, 0, NLM, NPAD, HD, HD, HD, NPAD, 0.125f, BH,BH,
           NLM*HD,0, SH,0, SS3,0);
        k_sm16k<<<BH*NLM,512>>>(sbuf);
        // t3 = S3 @ v  split-K over 32 chunks (TF32)
        TK(0,0,0, sbuf, v, part, 0, NLM, HD, KSPL, NPAD, HD, HD, 1.f, 0.f, BH*NSPL, BH,
           SS3, 512, SH, (long long)KSPL*HD, (long long)NLM*HD, (long long)BH*NLM*HD);
        k_red<<<(BH*NLM*HD+255)/256,256>>>();
        // w = pinv @ t3  (TF32)
        TK(0,0,0, zc, t3, w, 0, NLM, HD, NLM, NLM, HD, HD, 1.f, 0.f, BH,BH,
           65536,0, NLM*HD,0, NLM*HD,0);
        // S1 = softmax(0.125 * q @ kl^T)  [z][16384][256]  (bf16 GEMM)
        HK(0, q, kl, sbuf, 0, NPAD, NLM, HD, HD, HD, NLM, 0.125f, BH,BH,
           SH,0, NLM*HD,0, SS1,0);
        k_sm256w<<<(int)(((long long)BH*NPAD+7)/8),256>>>(sbuf, (long long)BH*NPAD);
        // ao = S1 @ w  -> [b][n][h*64+d]  (TF32)
        TK(0,0,0, sbuf, w, ao, 0, NPAD, HD, NLM, NLM, HD, DM, 1.f, 0.f, BH,8,
           SS1, 8ll*SS1, NLM*HD, 8ll*NLM*HD, HD, SD);
        // depthwise residual conv over v
        k_dw<<<dim3(NPAD/4,BH),dim3(64,4)>>>(rcw + l*264);
        // out projection + residual  (bf16 GEMM)
        HK(0, ao, aow + (long long)l*DM*DM, xln, aob + l*DM,
           NPAD, DM, DM, DM, DM, DM, 1.f, 2,2, SD,0, 0,0, SD,0);
        k_radd<<<(int)((2ll*NSEQ*DM+255)/256),256>>>();
        if (l == 0) {
            k_ppeg<<<dim3(NFEAT,2),512>>>(w7,b7,w5,b5,w3,b3);
            k_ppcp<<<(int)((2ll*NFEAT*DM+255)/256),256>>>();
        }
    }
    k_head<<<2,256>>>(nw, nb, f2w, f2b, out);
}

// round 15
// speedup vs baseline: 1.0400x; 1.0400x over previous
#include <cuda_runtime.h>
#include <cuda_bf16.h>
#include <math.h>
#include <stdint.h>

#define NSEQ 16130
#define NPAD 16384
#define PADF 254
#define NLM 256
#define DM 512
#define QW 1536
#define HD 64
#define BH 16
#define NTOK 16000
#define NFEAT 16129
#define GR 127
#define NSPL 32
#define KSPL 512

// ---------- static scratch ----------
__device__ float d_h[2ll*NSEQ*DM];
__device__ float d_xln[2ll*NPAD*DM];
__device__ float d_qkv[2ll*NPAD*QW];
__device__ float d_sbuf[(long long)BH*NPAD*NLM];
__device__ float d_ao[2ll*NPAD*DM];
__device__ float d_q[(long long)BH*NPAD*HD];
__device__ float d_k[(long long)BH*NPAD*HD];
__device__ float d_v[(long long)BH*NPAD*HD];
__device__ float d_part[(long long)NSPL*BH*NLM*HD];
__device__ float d_ql[BH*NLM*HD], d_kl[BH*NLM*HD];
__device__ float d_a2[BH*NLM*NLM], d_z[BH*NLM*NLM], d_z2[BH*NLM*NLM];
__device__ float d_az[BH*NLM*NLM], d_tt[BH*NLM*NLM], d_uu[BH*NLM*NLM];
__device__ float d_t3[BH*NLM*HD], d_w[BH*NLM*HD];
__device__ int d_sc[2];

__device__ __forceinline__ void ldsm4(uint32_t& r0, uint32_t& r1, uint32_t& r2, uint32_t& r3,
                                      uint32_t addr) {
    asm volatile("ldmatrix.sync.aligned.m8n8.x4.shared.b16 {%0,%1,%2,%3}, [%4];"
        : "=r"(r0), "=r"(r1), "=r"(r2), "=r"(r3) : "r"(addr));
}

// ---------- BF16 tensor-core GEMM, 128x128 tile, 2 CTA/SM, ldmatrix fragments ----------
// C = alpha * A @ B^T (+bias)(+relu); A [M][K] fp32, B [N][K] fp32; bf16 conversion at STS.
// Requires M%128==0, N%128==0, K%16==0, lda/ldb%4==0.
template<int RELU>
__global__ void __launch_bounds__(256) hk(
    const float* __restrict__ A, const float* __restrict__ B,
    float* __restrict__ C, const float* __restrict__ bias,
    int M, int N, int K, int lda, int ldb, int ldc, float alpha,
    int zm, long long sa1, long long sa2, long long sb1, long long sb2,
    long long sc1, long long sc2)
{
    int z = blockIdx.z, z1 = z % zm, z2 = z / zm;
    A += (long long)z1*sa1 + (long long)z2*sa2;
    B += (long long)z1*sb1 + (long long)z2*sb2;
    C += (long long)z1*sc1 + (long long)z2*sc2;

    __shared__ __nv_bfloat16 As[2][128][24];
    __shared__ __nv_bfloat16 Bs[2][128][24];

    int tid = threadIdx.x, lane = tid & 31, warp = tid >> 5;
    int wm = warp & 3, wn = warp >> 2;          // 4x2 warp grid: warp tile 32x64
    int m0 = blockIdx.y*128, n0 = blockIdx.x*128;

    float acc[2][8][4];
    #pragma unroll
    for (int a = 0; a < 2; a++)
        #pragma unroll
        for (int b = 0; b < 8; b++)
            #pragma unroll
            for (int cc = 0; cc < 4; cc++) acc[a][b][cc] = 0.f;

    float4 ra[2], rb[2];
    auto ldgT = [&](int k0) {
        #pragma unroll
        for (int j = 0; j < 2; j++) {
            int id = tid + j*256;
            int mm = id >> 2, kc = (id & 3)*4;
            ra[j] = *(const float4*)(A + (long long)(m0+mm)*lda + k0 + kc);
            rb[j] = *(const float4*)(B + (long long)(n0+mm)*ldb + k0 + kc);
        }
    };
    auto stsT = [&](int st) {
        #pragma unroll
        for (int j = 0; j < 2; j++) {
            int id = tid + j*256;
            int mm = id >> 2, kc = (id & 3)*4;
            __nv_bfloat162* da = (__nv_bfloat162*)&As[st][mm][kc];
            da[0] = __float22bfloat162_rn(make_float2(ra[j].x, ra[j].y));
            da[1] = __float22bfloat162_rn(make_float2(ra[j].z, ra[j].w));
            __nv_bfloat162* db = (__nv_bfloat162*)&Bs[st][mm][kc];
            db[0] = __float22bfloat162_rn(make_float2(rb[j].x, rb[j].y));
            db[1] = __float22bfloat162_rn(make_float2(rb[j].z, rb[j].w));
        }
    };

    // lane-dependent ldmatrix address components
    uint32_t aBase = (uint32_t)__cvta_generic_to_shared(&As[0][0][0]);
    uint32_t bBase = (uint32_t)__cvta_generic_to_shared(&Bs[0][0][0]);
    const int STG = 128*24*2;                 // bytes per stage
    int aRow = lane & 15,  aCol = (lane >> 4) * 8;
    int bRow = (lane & 7) + ((lane >> 4) << 3), bCol = ((lane >> 3) & 1) * 8;

    int nk = K >> 4;
    ldgT(0);
    stsT(0);
    __syncthreads();

    for (int kt = 0; kt < nk; kt++) {
        int cur = kt & 1;
        if (kt + 1 < nk) ldgT((kt+1)*16);
        uint32_t af[2][4];
        #pragma unroll
        for (int mt = 0; mt < 2; mt++) {
            int mb = wm*32 + mt*16;
            ldsm4(af[mt][0], af[mt][1], af[mt][2], af[mt][3],
                  aBase + cur*STG + (uint32_t)(((mb + aRow)*24 + aCol)*2));
        }
        uint32_t bf[8][2];
        #pragma unroll
        for (int j = 0; j < 4; j++) {
            int nb = wn*64 + j*16;
            ldsm4(bf[2*j][0], bf[2*j][1], bf[2*j+1][0], bf[2*j+1][1],
                  bBase + cur*STG + (uint32_t)(((nb + bRow)*24 + bCol)*2));
        }
        #pragma unroll
        for (int nt = 0; nt < 8; nt++) {
            #pragma unroll
            for (int mt = 0; mt < 2; mt++) {
                asm volatile(
                    "mma.sync.aligned.m16n8k16.row.col.f32.bf16.bf16.f32 "
                    "{%0,%1,%2,%3}, {%4,%5,%6,%7}, {%8,%9}, {%0,%1,%2,%3};"
                    : "+f"(acc[mt][nt][0]), "+f"(acc[mt][nt][1]),
                      "+f"(acc[mt][nt][2]), "+f"(acc[mt][nt][3])
                    : "r"(af[mt][0]), "r"(af[mt][1]), "r"(af[mt][2]), "r"(af[mt][3]),
                      "r"(bf[nt][0]), "r"(bf[nt][1]));
            }
        }
        if (kt + 1 < nk) stsT(cur ^ 1);
        __syncthreads();
    }
    int r = lane >> 2, c2 = (lane & 3)*2;
    #pragma unroll
    for (int mt = 0; mt < 2; mt++) {
        #pragma unroll
        for (int nt = 0; nt < 8; nt++) {
            int row = m0 + wm*32 + mt*16 + r;
            int col = n0 + wn*64 + nt*8 + c2;
            float bv0 = bias ? bias[col] : 0.f;
            float bv1 = bias ? bias[col+1] : 0.f;
            float v0 = alpha*acc[mt][nt][0] + bv0;
            float v1 = alpha*acc[mt][nt][1] + bv1;
            float v2 = alpha*acc[mt][nt][2] + bv0;
            float v3 = alpha*acc[mt][nt][3] + bv1;
            if (RELU) { v0=fmaxf(v0,0.f); v1=fmaxf(v1,0.f); v2=fmaxf(v2,0.f); v3=fmaxf(v3,0.f); }
            C[(long long)row*ldc + col]       = v0;
            C[(long long)row*ldc + col+1]     = v1;
            C[(long long)(row+8)*ldc + col]   = v2;
            C[(long long)(row+8)*ldc + col+1] = v3;
        }
    }
}

// ---------- TF32 tensor-core GEMM (pinv chain / NN shapes / attn2) ----------
template<int TB, int RELU, int BN, int DB>
__global__ void __launch_bounds__(256) tk(
    const float* __restrict__ A, const float* __restrict__ B,
    float* __restrict__ C, const float* __restrict__ bias,
    int M, int N, int K, int lda, int ldb, int ldc, float alpha, float cd,
    int zm, long long sa1, long long sa2, long long sb1, long long sb2,
    long long sc1, long long sc2)
{
    int z = blockIdx.z, z1 = z % zm, z2 = z / zm;
    A += (long long)z1*sa1 + (long long)z2*sa2;
    B += (long long)z1*sb1 + (long long)z2*sb2;
    C += (long long)z1*sc1 + (long long)z2*sc2;

    __shared__ float As[2][128][20];
    constexpr int BS_R = TB ? BN : 16;
    constexpr int BS_C = TB ? 20 : (BN + 8);
    __shared__ float Bs[2][BS_R][BS_C];
    constexpr int NB4 = BN/64;

    int tid = threadIdx.x, lane = tid & 31, warp = tid >> 5;
    int wm = warp & 3, wn = warp >> 2;
    constexpr int WN = BN/2, NT = WN/8;
    int m0 = blockIdx.y*128, n0 = blockIdx.x*BN;

    float acc[2][NT][4];
    #pragma unroll
    for (int a = 0; a < 2; a++)
        #pragma unroll
        for (int b = 0; b < NT; b++)
            #pragma unroll
            for (int cc = 0; cc < 4; cc++) acc[a][b][cc] = 0.f;

    float4 ra[2], rb[NB4];
    auto ldgT = [&](int k0) {
        #pragma unroll
        for (int j = 0; j < 2; j++) {
            int id = tid + j*256;
            int mm = id >> 2, kc = (id & 3)*4;
            ra[j] = *(const float4*)(A + (long long)(m0+mm)*lda + k0 + kc);
        }
        if (TB) {
            #pragma unroll
            for (int j = 0; j < NB4; j++) {
                int id = tid + j*256;
                int nn = id >> 2, kc = (id & 3)*4;
                rb[j] = *(const float4*)(B + (long long)(n0+nn)*ldb + k0 + kc);
            }
        } else {
            #pragma unroll
            for (int j = 0; j < NB4; j++) {
                int id = tid + j*256;
                int kk = id / (BN/4), nc = (id % (BN/4))*4;
                rb[j] = *(const float4*)(B + (long long)(k0+kk)*ldb + n0 + nc);
            }
        }
    };
    auto stsT = [&](int st) {
        #pragma unroll
        for (int j = 0; j < 2; j++) {
            int id = tid + j*256;
            int mm = id >> 2, kc = (id & 3)*4;
            *(float4*)&As[st][mm][kc] = ra[j];
        }
        if (TB) {
            #pragma unroll
            for (int j = 0; j < NB4; j++) {
                int id = tid + j*256;
                int nn = id >> 2, kc = (id & 3)*4;
                *(float4*)&Bs[st][nn][kc] = rb[j];
            }
        } else {
            #pragma unroll
            for (int j = 0; j < NB4; j++) {
                int id = tid + j*256;
                int kk = id / (BN/4), nc = (id % (BN/4))*4;
                *(float4*)&Bs[st][kk][nc] = rb[j];
            }
        }
    };

    int nk = K >> 4;
    ldgT(0);
    stsT(0);
    __syncthreads();

    for (int kt = 0; kt < nk; kt++) {
        int cur = kt & 1;
        if (kt + 1 < nk) ldgT((kt+1)*16);
        int k0 = kt*16;
        int r = lane >> 2, c = lane & 3;
        #pragma unroll
        for (int ks = 0; ks < 2; ks++) {
            int kb = ks*8;
            uint32_t af[2][4];
            #pragma unroll
            for (int mt = 0; mt < 2; mt++) {
                int mb = wm*32 + mt*16;
                af[mt][0] = __float_as_uint(As[cur][mb+r  ][kb+c  ]);
                af[mt][1] = __float_as_uint(As[cur][mb+r+8][kb+c  ]);
                af[mt][2] = __float_as_uint(As[cur][mb+r  ][kb+c+4]);
                af[mt][3] = __float_as_uint(As[cur][mb+r+8][kb+c+4]);
            }
            #pragma unroll
            for (int nt = 0; nt < NT; nt++) {
                int nb = wn*WN + nt*8;
                uint32_t b0, b1;
                if (TB) {
                    b0 = __float_as_uint(Bs[cur][nb+r][kb+c  ]);
                    b1 = __float_as_uint(Bs[cur][nb+r][kb+c+4]);
                } else {
                    float f0 = Bs[cur][kb+c  ][nb+r];
                    float f1 = Bs[cur][kb+c+4][nb+r];
                    if (DB) {
                        int ng = n0 + nb + r;
                        f0 = ((k0+kb+c  ) == ng ? cd : 0.f) - f0;
                        f1 = ((k0+kb+c+4) == ng ? cd : 0.f) - f1;
                    }
                    b0 = __float_as_uint(f0);
                    b1 = __float_as_uint(f1);
                }
                #pragma unroll
                for (int mt = 0; mt < 2; mt++) {
                    asm volatile(
                        "mma.sync.aligned.m16n8k8.row.col.f32.tf32.tf32.f32 "
                        "{%0,%1,%2,%3}, {%4,%5,%6,%7}, {%8,%9}, {%0,%1,%2,%3};"
                        : "+f"(acc[mt][nt][0]), "+f"(acc[mt][nt][1]),
                          "+f"(acc[mt][nt][2]), "+f"(acc[mt][nt][3])
                        : "r"(af[mt][0]), "r"(af[mt][1]), "r"(af[mt][2]), "r"(af[mt][3]),
                          "r"(b0), "r"(b1));
                }
            }
        }
        if (kt + 1 < nk) stsT(cur ^ 1);
        __syncthreads();
    }
    int r = lane >> 2, c2 = (lane & 3)*2;
    #pragma unroll
    for (int mt = 0; mt < 2; mt++) {
        #pragma unroll
        for (int nt = 0; nt < NT; nt++) {
            int row = m0 + wm*32 + mt*16 + r;
            int col = n0 + wn*WN + nt*8 + c2;
            float bv0 = bias ? bias[col] : 0.f;
            float bv1 = bias ? bias[col+1] : 0.f;
            float v0 = alpha*acc[mt][nt][0] + bv0;
            float v1 = alpha*acc[mt][nt][1] + bv1;
            float v2 = alpha*acc[mt][nt][2] + bv0;
            float v3 = alpha*acc[mt][nt][3] + bv1;
            if (RELU) { v0=fmaxf(v0,0.f); v1=fmaxf(v1,0.f); v2=fmaxf(v2,0.f); v3=fmaxf(v3,0.f); }
            C[(long long)row*ldc + col]       = v0;
            C[(long long)row*ldc + col+1]     = v1;
            C[(long long)(row+8)*ldc + col]   = v2;
            C[(long long)(row+8)*ldc + col+1] = v3;
        }
    }
}

// ---------- small kernels ----------
__global__ void k_buildh(const float* __restrict__ fc1o, const float* __restrict__ cls) {
    long long idx = blockIdx.x*256ll + threadIdx.x;
    if (idx >= 2ll*NSEQ*DM) return;
    int c = (int)(idx % DM); long long r = idx / DM; int b = (int)(r / NSEQ); int i = (int)(r % NSEQ);
    float v;
    if (i == 0) v = cls[c];
    else { int t = i-1; if (t >= NTOK) t -= NTOK; v = fc1o[((long long)b*NTOK + t)*DM + c]; }
    d_h[idx] = v;
}

__global__ void k_lnpad(const float* __restrict__ w, const float* __restrict__ bia) {
    int r = blockIdx.x; int b = r / NPAD, rr = r % NPAD;
    float* o = d_xln + (long long)r*DM;
    int t = threadIdx.x;
    if (rr < PADF) { o[t] = 0.f; o[t+256] = 0.f; return; }
    const float* in = d_h + ((long long)b*NSEQ + rr - PADF)*DM;
    __shared__ float red[256];
    float v0 = in[t], v1 = in[t+256];
    red[t] = v0+v1; __syncthreads();
    for (int s = 128; s > 0; s >>= 1) { if (t < s) red[t] += red[t+s]; __syncthreads(); }
    float mu = red[0]*(1.f/DM); __syncthreads();
    float e0 = v0-mu, e1 = v1-mu;
    red[t] = e0*e0+e1*e1; __syncthreads();
    for (int s = 128; s > 0; s >>= 1) { if (t < s) red[t] += red[t+s]; __syncthreads(); }
    float rstd = rsqrtf(red[0]*(1.f/DM) + 1e-5f);
    o[t]     = e0*rstd*w[t]     + bia[t];
    o[t+256] = e1*rstd*w[t+256] + bia[t+256];
}

__global__ void k_splitqkv4() {
    long long idx = blockIdx.x*256ll + threadIdx.x;
    if (idx >= 2ll*NPAD*DM/4) return;
    int c4 = (int)(idx % 128);
    long long bn = idx / 128;
    int hh = c4 >> 4, d4 = c4 & 15;
    int b = (int)(bn / NPAD), n = (int)(bn % NPAD);
    const float4* src = (const float4*)(d_qkv + bn*QW) + c4;
    long long dst = (((long long)(b*8+hh)*NPAD) + n)*(HD/4) + d4;
    ((float4*)d_q)[dst] = src[0];
    ((float4*)d_k)[dst] = src[DM/4];
    ((float4*)d_v)[dst] = src[2*DM/4];
}

__global__ void k_lm() {
    int z = blockIdx.y, j = blockIdx.x, dd = threadIdx.x;
    const float* q = d_q + ((long long)z*NPAD + j*64)*HD + dd;
    const float* k = d_k + ((long long)z*NPAD + j*64)*HD + dd;
    float sq = 0.f, sk = 0.f;
    #pragma unroll 8
    for (int i = 0; i < 64; i++) { sq += q[i*HD]; sk += k[i*HD]; }
    d_ql[(z*NLM+j)*HD+dd] = sq*(1.f/64.f);
    d_kl[(z*NLM+j)*HD+dd] = sk*(1.f/64.f);
}

__global__ void __launch_bounds__(512) k_sm16k(float* __restrict__ p) {
    float4* p4 = (float4*)(p + (long long)blockIdx.x * NPAD);
    int t = threadIdx.x;
    __shared__ float red[512];
    float4 va[8];
    float m = -1e30f;
    #pragma unroll
    for (int j = 0; j < 8; j++) {
        va[j] = p4[t + j*512];
        m = fmaxf(m, fmaxf(fmaxf(va[j].x, va[j].y), fmaxf(va[j].z, va[j].w)));
    }
    red[t] = m; __syncthreads();
    for (int s = 256; s > 0; s >>= 1) { if (t < s) red[t] = fmaxf(red[t], red[t+s]); __syncthreads(); }
    m = red[0]; __syncthreads();
    float sum = 0.f;
    #pragma unroll
    for (int j = 0; j < 8; j++) {
        va[j].x = __expf(va[j].x - m); va[j].y = __expf(va[j].y - m);
        va[j].z = __expf(va[j].z - m); va[j].w = __expf(va[j].w - m);
        sum += (va[j].x + va[j].y) + (va[j].z + va[j].w);
    }
    red[t] = sum; __syncthreads();
    for (int s = 256; s > 0; s >>= 1) { if (t < s) red[t] += red[t+s]; __syncthreads(); }
    float inv = 1.f/red[0];
    #pragma unroll
    for (int j = 0; j < 8; j++) {
        va[j].x *= inv; va[j].y *= inv; va[j].z *= inv; va[j].w *= inv;
        p4[t + j*512] = va[j];
    }
}

__global__ void k_sm256w(float* __restrict__ p, long long nrows) {
    long long row = blockIdx.x*8ll + (threadIdx.x >> 5);
    if (row >= nrows) return;
    int lane = threadIdx.x & 31;
    float4* p4 = (float4*)(p + row*NLM);
    float4 u0 = p4[lane], u1 = p4[lane+32];
    float m = fmaxf(fmaxf(fmaxf(u0.x,u0.y),fmaxf(u0.z,u0.w)),
                    fmaxf(fmaxf(u1.x,u1.y),fmaxf(u1.z,u1.w)));
    #pragma unroll
    for (int s = 16; s > 0; s >>= 1) m = fmaxf(m, __shfl_xor_sync(0xffffffffu, m, s));
    u0.x=__expf(u0.x-m); u0.y=__expf(u0.y-m); u0.z=__expf(u0.z-m); u0.w=__expf(u0.w-m);
    u1.x=__expf(u1.x-m); u1.y=__expf(u1.y-m); u1.z=__expf(u1.z-m); u1.w=__expf(u1.w-m);
    float sum = (u0.x+u0.y)+(u0.z+u0.w)+(u1.x+u1.y)+(u1.z+u1.w);
    #pragma unroll
    for (int s = 16; s > 0; s >>= 1) sum += __shfl_xor_sync(0xffffffffu, sum, s);
    float inv = 1.f/sum;
    u0.x*=inv; u0.y*=inv; u0.z*=inv; u0.w*=inv;
    u1.x*=inv; u1.y*=inv; u1.z*=inv; u1.w*=inv;
    p4[lane] = u0; p4[lane+32] = u1;
}

__global__ void k_init() { d_sc[0] = 0; d_sc[1] = 0; }

__global__ void k_rmax() {
    int mb = blockIdx.x >> 8, i = blockIdx.x & 255, t = threadIdx.x;
    __shared__ float red[256];
    red[t] = fabsf(d_a2[((long long)mb*256+i)*256 + t]); __syncthreads();
    for (int s = 128; s > 0; s >>= 1) { if (t < s) red[t] += red[t+s]; __syncthreads(); }
    if (t == 0) atomicMax(&d_sc[0], __float_as_int(red[0]));
}

__global__ void k_cmax() {
    int mb = blockIdx.x, j = threadIdx.x;
    float s = 0.f;
    for (int i = 0; i < 256; i++) s += fabsf(d_a2[((long long)mb*256+i)*256 + j]);
    atomicMax(&d_sc[1], __float_as_int(s));
}

__global__ void k_tz() {
    long long idx = blockIdx.x*256ll + threadIdx.x;
    if (idx >= (long long)BH*65536) return;
    int mb = (int)(idx >> 16); int r = (int)((idx >> 8) & 255); int c = (int)(idx & 255);
    float sc = __int_as_float(d_sc[0]) * __int_as_float(d_sc[1]);
    d_z[idx] = d_a2[(long long)mb*65536 + (long long)c*256 + r] / sc;
}

__global__ void k_red() {
    int idx = blockIdx.x*256 + threadIdx.x;
    if (idx >= BH*NLM*HD) return;
    float s = 0.f;
    #pragma unroll
    for (int p = 0; p < NSPL; p++) s += d_part[(long long)p*BH*NLM*HD + idx];
    d_t3[idx] = s;
}

__global__ void k_dw(const float* __restrict__ w) {
    int z = blockIdx.y; int b = z >> 3, hh = z & 7;
    int i = blockIdx.x*4 + threadIdx.y;
    int dd = threadIdx.x;
    const float* v = d_v + (long long)z*NPAD*HD + dd;
    float s = 0.f;
    #pragma unroll
    for (int tp = 0; tp < 33; tp++) {
        int ii = i + tp - 16;
        if (ii >= 0 && ii < NPAD) s += w[hh*33+tp] * v[(long long)ii*HD];
    }
    d_ao[((long long)b*NPAD + i)*DM + hh*HD + dd] += s;
}

__global__ void k_radd() {
    long long idx = blockIdx.x*256ll + threadIdx.x;
    if (idx >= 2ll*NSEQ*DM) return;
    int c = (int)(idx % DM); long long r = idx / DM; int b = (int)(r / NSEQ); int i = (int)(r % NSEQ);
    d_h[idx] += d_xln[((long long)b*NPAD + PADF + i)*DM + c];
}

__global__ void k_ppeg(const float* __restrict__ w7, const float* __restrict__ b7,
                       const float* __restrict__ w5, const float* __restrict__ b5,
                       const float* __restrict__ w3, const float* __restrict__ b3) {
    int p = blockIdx.x, b = blockIdx.y, c = threadIdx.x;
    int r = p / GR, ww = p % GR;
    const float* base = d_h + ((long long)b*NSEQ + 1)*DM + c;
    float acc = base[(long long)p*DM] + b7[c] + b5[c] + b3[c];
    for (int i = 0; i < 7; i++) {
        int rr = r + i - 3; if (rr < 0 || rr >= GR) continue;
        for (int j = 0; j < 7; j++) {
            int cc = ww + j - 3; if (cc < 0 || cc >= GR) continue;
            float x = base[(long long)(rr*GR+cc)*DM];
            acc += w7[c*49 + i*7 + j] * x;
            if (i >= 1 && i < 6 && j >= 1 && j < 6) acc += w5[c*25 + (i-1)*5 + (j-1)] * x;
            if (i >= 2 && i < 5 && j >= 2 && j < 5) acc += w3[c*9 + (i-2)*3 + (j-2)] * x;
        }
    }
    d_xln[((long long)b*NFEAT + p)*DM + c] = acc;
}

__global__ void k_ppcp() {
    long long idx = blockIdx.x*256ll + threadIdx.x;
    if (idx >= 2ll*NFEAT*DM) return;
    int c = (int)(idx % DM); long long r = idx / DM; int b = (int)(r / NFEAT); int p = (int)(r % NFEAT);
    d_h[((long long)b*NSEQ + 1 + p)*DM + c] = d_xln[idx];
}

__global__ void k_head(const float* __restrict__ nw, const float* __restrict__ nb,
                       const float* __restrict__ f2w, const float* __restrict__ f2b,
                       float* __restrict__ out) {
    int b = blockIdx.x, t = threadIdx.x;
    const float* x = d_h + (long long)b*NSEQ*DM;
    __shared__ float red[256];
    float v0 = x[t], v1 = x[t+256];
    red[t] = v0+v1; __syncthreads();
    for (int s = 128; s > 0; s >>= 1) { if (t < s) red[t] += red[t+s]; __syncthreads(); }
    float mu = red[0]*(1.f/DM); __syncthreads();
    float e0 = v0-mu, e1 = v1-mu;
    red[t] = e0*e0+e1*e1; __syncthreads();
    for (int s = 128; s > 0; s >>= 1) { if (t < s) red[t] += red[t+s]; __syncthreads(); }
    float rstd = rsqrtf(red[0]*(1.f/DM) + 1e-5f);
    __syncthreads();
    float n0 = e0*rstd*nw[t] + nb[t], n1 = e1*rstd*nw[t+256] + nb[t+256];
    for (int j = 0; j < 2; j++) {
        red[t] = n0*f2w[j*DM+t] + n1*f2w[j*DM+t+256]; __syncthreads();
        for (int s = 128; s > 0; s >>= 1) { if (t < s) red[t] += red[t+s]; __syncthreads(); }
        if (t == 0) out[b*2+j] = red[0] + f2b[j];
        __syncthreads();
    }
}

// ---------- host wrappers ----------
static inline void HK(int RELU, const float* A, const float* B, float* C, const float* bias,
                      int M, int N, int K, int lda, int ldb, int ldc, float al,
                      int Z, int zm,
                      long long a1, long long a2, long long b1, long long b2,
                      long long c1, long long c2) {
    dim3 g(N/128, M/128, Z);
    if (RELU) hk<1><<<g,256>>>(A,B,C,bias,M,N,K,lda,ldb,ldc,al,zm,a1,a2,b1,b2,c1,c2);
    else      hk<0><<<g,256>>>(A,B,C,bias,M,N,K,lda,ldb,ldc,al,zm,a1,a2,b1,b2,c1,c2);
}
static inline void TK(int TB, int RELU, int DB,
                      const float* A, const float* B, float* C, const float* bias,
                      int M, int N, int K, int lda, int ldb, int ldc, float al, float cd,
                      int Z, int zm,
                      long long a1, long long a2, long long b1, long long b2,
                      long long c1, long long c2) {
    if (N % 128 == 0) {
        dim3 g(N/128, M/128, Z);
        if (TB && RELU) tk<1,1,128,0><<<g,256>>>(A,B,C,bias,M,N,K,lda,ldb,ldc,al,cd,zm,a1,a2,b1,b2,c1,c2);
        else if (TB)    tk<1,0,128,0><<<g,256>>>(A,B,C,bias,M,N,K,lda,ldb,ldc,al,cd,zm,a1,a2,b1,b2,c1,c2);
        else if (DB)    tk<0,0,128,1><<<g,256>>>(A,B,C,bias,M,N,K,lda,ldb,ldc,al,cd,zm,a1,a2,b1,b2,c1,c2);
        else            tk<0,0,128,0><<<g,256>>>(A,B,C,bias,M,N,K,lda,ldb,ldc,al,cd,zm,a1,a2,b1,b2,c1,c2);
    } else {
        dim3 g(N/64, M/128, Z);
        tk<0,0,64,0><<<g,256>>>(A,B,C,bias,M,N,K,lda,ldb,ldc,al,cd,zm,a1,a2,b1,b2,c1,c2);
    }
}

extern "C" void kernel_launch(void* const* d_in, const int* in_sizes, int n_in,
                              void* d_out, int out_size) {
    const float* x    = (const float*)d_in[0];
    const float* fc1w = (const float*)d_in[1];
    const float* fc1b = (const float*)d_in[2];
    const float* cls  = (const float*)d_in[3];
    const float* lnw  = (const float*)d_in[4];
    const float* lnb  = (const float*)d_in[5];
    const float* qkvw = (const float*)d_in[6];
    const float* qkvb = (const float*)d_in[7];
    const float* aow  = (const float*)d_in[8];
    const float* aob  = (const float*)d_in[9];
    const float* rcw  = (const float*)d_in[10];
    const float* w7 = (const float*)d_in[11]; const float* b7 = (const float*)d_in[12];
    const float* w5 = (const float*)d_in[13]; const float* b5 = (const float*)d_in[14];
    const float* w3 = (const float*)d_in[15]; const float* b3 = (const float*)d_in[16];
    const float* nw = (const float*)d_in[17]; const float* nb = (const float*)d_in[18];
    const float* f2w = (const float*)d_in[19]; const float* f2b = (const float*)d_in[20];
    float* out = (float*)d_out;

    float *xln, *qkv, *sbuf, *ao, *q, *k, *v, *part;
    float *ql, *kl, *a2, *z, *z2, *az, *tt, *uu, *t3, *w;
    cudaGetSymbolAddress((void**)&xln, d_xln);
    cudaGetSymbolAddress((void**)&qkv, d_qkv);
    cudaGetSymbolAddress((void**)&sbuf, d_sbuf);
    cudaGetSymbolAddress((void**)&ao, d_ao);
    cudaGetSymbolAddress((void**)&q, d_q);
    cudaGetSymbolAddress((void**)&k, d_k);
    cudaGetSymbolAddress((void**)&v, d_v);
    cudaGetSymbolAddress((void**)&part, d_part);
    cudaGetSymbolAddress((void**)&ql, d_ql);
    cudaGetSymbolAddress((void**)&kl, d_kl);
    cudaGetSymbolAddress((void**)&a2, d_a2);
    cudaGetSymbolAddress((void**)&z, d_z);
    cudaGetSymbolAddress((void**)&z2, d_z2);
    cudaGetSymbolAddress((void**)&az, d_az);
    cudaGetSymbolAddress((void**)&tt, d_tt);
    cudaGetSymbolAddress((void**)&uu, d_uu);
    cudaGetSymbolAddress((void**)&t3, d_t3);
    cudaGetSymbolAddress((void**)&w, d_w);

    const long long SQ  = (long long)NPAD*QW;
    const long long SD  = (long long)NPAD*DM;
    const long long SH  = (long long)NPAD*HD;
    const long long SS3 = (long long)NLM*NPAD;
    const long long SS1 = (long long)NPAD*NLM;

    // fc1 + relu (bf16) -> sbuf (32000,512); then assemble token stream h
    HK(1, x, fc1w, sbuf, fc1b, 2*NTOK, DM, 1024, 1024, 1024, DM, 1.f, 1,1, 0,0,0,0,0,0);
    k_buildh<<<(int)((2ll*NSEQ*DM+255)/256),256>>>(sbuf, cls);

    for (int l = 0; l < 2; l++) {
        k_lnpad<<<2*NPAD,256>>>(lnw + l*DM, lnb + l*DM);
        HK(0, xln, qkvw + (long long)l*QW*DM, qkv, qkvb + l*QW,
           NPAD, QW, DM, DM, DM, QW, 1.f, 2,2, SD,0, 0,0, SQ,0);
        k_splitqkv4<<<(int)((2ll*NPAD*DM/4+255)/256),256>>>();
        k_lm<<<dim3(256,16),64>>>();
        // attn2 = softmax(0.125 * ql @ kl^T)  (TF32)
        TK(1,0,0, ql, kl, a2, 0, NLM, NLM, HD, HD, HD, NLM, 0.125f, 0.f, BH,BH,
           NLM*HD,0, NLM*HD,0, NLM*NLM,0);
        k_sm256w<<<(int)((BH*NLM+7)/8),256>>>(a2, (long long)BH*NLM);
        // pinv(attn2) (TF32, elementwise fused into B fragment loads)
        k_init<<<1,1>>>();
        k_rmax<<<BH*NLM,256>>>();
        k_cmax<<<BH,256>>>();
        k_tz<<<(BH*65536+255)/256,256>>>();
        float* zc = z; float* zn = z2;
        for (int it = 0; it < 6; it++) {
            TK(0,0,0, a2, zc, az, 0, NLM,NLM,NLM, NLM,NLM,NLM, 1.f, 0.f, BH,BH, 65536,0,65536,0,65536,0);
            TK(0,0,1, az, az, tt, 0, NLM,NLM,NLM, NLM,NLM,NLM, 1.f, 7.f, BH,BH, 65536,0,65536,0,65536,0);
            TK(0,0,1, az, tt, uu, 0, NLM,NLM,NLM, NLM,NLM,NLM, 1.f, 15.f, BH,BH, 65536,0,65536,0,65536,0);
            TK(0,0,1, zc, uu, zn, 0, NLM,NLM,NLM, NLM,NLM,NLM, 0.25f, 13.f, BH,BH, 65536,0,65536,0,65536,0);
            float* sw = zc; zc = zn; zn = sw;
        }
        // S3 = softmax(0.125 * ql @ k^T)   [z][256][16384]  (bf16 GEMM)
        HK(0, ql, k, sbuf, 0, NLM, NPAD, HD, HD, HD, NPAD, 0.125f, BH,BH,
           NLM*HD,0, SH,0, SS3,0);
        k_sm16k<<<BH*NLM,512>>>(sbuf);
        // t3 = S3 @ v  split-K over 32 chunks (TF32)
        TK(0,0,0, sbuf, v, part, 0, NLM, HD, KSPL, NPAD, HD, HD, 1.f, 0.f, BH*NSPL, BH,
           SS3, 512, SH, (long long)KSPL*HD, (long long)NLM*HD, (long long)BH*NLM*HD);
        k_red<<<(BH*NLM*HD+255)/256,256>>>();
        // w = pinv @ t3  (TF32)
        TK(0,0,0, zc, t3, w, 0, NLM, HD, NLM, NLM, HD, HD, 1.f, 0.f, BH,BH,
           65536,0, NLM*HD,0, NLM*HD,0);
        // S1 = softmax(0.125 * q @ kl^T)  [z][16384][256]  (bf16 GEMM)
        HK(0, q, kl, sbuf, 0, NPAD, NLM, HD, HD, HD, NLM, 0.125f, BH,BH,
           SH,0, NLM*HD,0, SS1,0);
        k_sm256w<<<(int)(((long long)BH*NPAD+7)/8),256>>>(sbuf, (long long)BH*NPAD);
        // ao = S1 @ w  -> [b][n][h*64+d]  (TF32)
        TK(0,0,0, sbuf, w, ao, 0, NPAD, HD, NLM, NLM, HD, DM, 1.f, 0.f, BH,8,
           SS1, 8ll*SS1, NLM*HD, 8ll*NLM*HD, HD, SD);
        // depthwise residual conv over v
        k_dw<<<dim3(NPAD/4,BH),dim3(64,4)>>>(rcw + l*264);
        // out projection + residual  (bf16 GEMM)
        HK(0, ao, aow + (long long)l*DM*DM, xln, aob + l*DM,
           NPAD, DM, DM, DM, DM, DM, 1.f, 2,2, SD,0, 0,0, SD,0);
        k_radd<<<(int)((2ll*NSEQ*DM+255)/256),256>>>();
        if (l == 0) {
            k_ppeg<<<dim3(NFEAT,2),512>>>(w7,b7,w5,b5,w3,b3);
            k_ppcp<<<(int)((2ll*NFEAT*DM+255)/256),256>>>();
        }
    }
    k_head<<<2,256>>>(nw, nb, f2w, f2b, out);
}